// round 1
// baseline (speedup 1.0000x reference)
#include <cuda_runtime.h>
#include <cstdint>
#include <math.h>

#define C 128
#define MAXN 100000

// Scratch: per-node, per-channel running max of edge messages. -inf = "no edge yet".
__device__ float g_maxbuf[(size_t)MAXN * C];

// ---------------------------------------------------------------------------
// Kernel 1: init g_maxbuf to -inf
// ---------------------------------------------------------------------------
__global__ void init_kernel(int total4) {
    int i = blockIdx.x * blockDim.x + threadIdx.x;
    if (i < total4) {
        const float ninf = __int_as_float(0xFF800000);
        ((float4*)g_maxbuf)[i] = make_float4(ninf, ninf, ninf, ninf);
    }
}

// ---------------------------------------------------------------------------
// Kernel 2: edge messages + segment max via float atomic-max bit trick.
// One warp per edge; lane l owns channels [4l, 4l+4).
// Monotone filter: values in g_maxbuf only increase, so skipping when a
// (possibly stale) read already >= v is race-safe.
// ---------------------------------------------------------------------------
__device__ __forceinline__ void atomic_max_float(float* addr, float v, float cur) {
    if (v > cur) {
        if (v >= 0.0f)
            atomicMax((int*)addr, __float_as_int(v));
        else
            atomicMin((unsigned int*)addr, __float_as_uint(v));
    }
}

__global__ void edge_kernel(const float* __restrict__ x,
                            const int* __restrict__ src,
                            const int* __restrict__ dst,
                            int E) {
    int widx = (int)((blockIdx.x * (long long)blockDim.x + threadIdx.x) >> 5);
    if (widx >= E) return;
    int lane = threadIdx.x & 31;

    int s = __ldg(src + widx);
    int d = __ldg(dst + widx);

    float4 xs = __ldg((const float4*)(x + (size_t)s * C) + lane);
    float4 xd = __ldg((const float4*)(x + (size_t)d * C) + lane);

    float* mp = g_maxbuf + (size_t)d * C + lane * 4;
    float4 cur = *(const float4*)mp;  // racy but monotone -> safe filter

    atomic_max_float(mp + 0, xd.x - xs.x, cur.x);
    atomic_max_float(mp + 1, xd.y - xs.y, cur.y);
    atomic_max_float(mp + 2, xd.z - xs.z, cur.z);
    atomic_max_float(mp + 3, xd.w - xs.w, cur.w);
}

// ---------------------------------------------------------------------------
// Kernel 3: out = relu([x | fix(maxbuf)] @ W + b)
// BM=64, BN=128 (full), BK=16. 256 threads, each computes 8 rows x 4 cols.
// ---------------------------------------------------------------------------
#define BM 64
#define BK 16
#define BN 128

__global__ void gemm_kernel(const float* __restrict__ x,
                            const float* __restrict__ W,
                            const float* __restrict__ bias,
                            float* __restrict__ out,
                            int N) {
    __shared__ float As[BM][BK + 1];
    __shared__ float Bs[BK][BN];

    int t  = threadIdx.x;
    int m0 = blockIdx.x * BM;
    int tc = t & 31;        // 32 col-groups of 4
    int tr = t >> 5;        // 8 row-groups of 8
    int c0 = tc * 4;
    int r0 = tr * 8;

    float acc[8][4];
#pragma unroll
    for (int r = 0; r < 8; r++)
#pragma unroll
        for (int j = 0; j < 4; j++) acc[r][j] = 0.0f;

    for (int k0 = 0; k0 < 2 * C; k0 += BK) {
        // Load A tile: 64x16 = 1024 elems, 4 per thread.
        // Columns k<128 come from x, k>=128 from g_maxbuf with -inf -> 0.
#pragma unroll
        for (int i = 0; i < 4; i++) {
            int idx = t + i * 256;
            int mm  = idx >> 4;
            int kk  = idx & 15;
            int gm  = m0 + mm;
            int gk  = k0 + kk;
            float v = 0.0f;
            if (gm < N) {
                if (gk < C) {
                    v = __ldg(x + (size_t)gm * C + gk);
                } else {
                    v = g_maxbuf[(size_t)gm * C + (gk - C)];
                    if (isinf(v)) v = 0.0f;  // only -inf possible
                }
            }
            As[mm][kk] = v;
        }
        // Load B tile: 16x128 = 2048 elems, 8 per thread, fully coalesced.
#pragma unroll
        for (int i = 0; i < 8; i++) {
            int idx = t + i * 256;
            int nn  = idx & 127;
            int kk  = idx >> 7;
            Bs[kk][nn] = __ldg(W + (size_t)(k0 + kk) * BN + nn);
        }
        __syncthreads();

#pragma unroll
        for (int kk = 0; kk < BK; kk++) {
            float4 bv = *(const float4*)&Bs[kk][c0];
#pragma unroll
            for (int r = 0; r < 8; r++) {
                float a = As[r0 + r][kk];  // warp-uniform -> LDS broadcast
                acc[r][0] = fmaf(a, bv.x, acc[r][0]);
                acc[r][1] = fmaf(a, bv.y, acc[r][1]);
                acc[r][2] = fmaf(a, bv.z, acc[r][2]);
                acc[r][3] = fmaf(a, bv.w, acc[r][3]);
            }
        }
        __syncthreads();
    }

    float4 bv = __ldg((const float4*)bias + tc);
#pragma unroll
    for (int r = 0; r < 8; r++) {
        int gm = m0 + r0 + r;
        if (gm < N) {
            float4 o;
            o.x = fmaxf(acc[r][0] + bv.x, 0.0f);
            o.y = fmaxf(acc[r][1] + bv.y, 0.0f);
            o.z = fmaxf(acc[r][2] + bv.z, 0.0f);
            o.w = fmaxf(acc[r][3] + bv.w, 0.0f);
            *(float4*)(out + (size_t)gm * BN + c0) = o;
        }
    }
}

// ---------------------------------------------------------------------------
// Launch
// ---------------------------------------------------------------------------
extern "C" void kernel_launch(void* const* d_in, const int* in_sizes, int n_in,
                              void* d_out, int out_size) {
    const float* x    = (const float*)d_in[0];
    const float* W    = (const float*)d_in[1];
    const float* bias = (const float*)d_in[2];
    const int*   src  = (const int*)d_in[3];
    const int*   dst  = (const int*)d_in[4];
    float*       out  = (float*)d_out;

    int N = in_sizes[0] / C;      // 100000
    int E = in_sizes[3];          // 1600000

    int total4 = N * (C / 4);
    init_kernel<<<(total4 + 255) / 256, 256>>>(total4);

    long long threads = (long long)E * 32;
    int eblocks = (int)((threads + 255) / 256);
    edge_kernel<<<eblocks, 256>>>(x, src, dst, E);

    int gblocks = (N + BM - 1) / BM;
    gemm_kernel<<<gblocks, 256>>>(x, W, bias, out, N);
}

// round 2
// speedup vs baseline: 1.1085x; 1.1085x over previous
#include <cuda_runtime.h>
#include <cstdint>
#include <math.h>

#define C 128
#define MAXN 100000
#define MAXE 1600000

// ---------------------------------------------------------------------------
// Scratch
// ---------------------------------------------------------------------------
__device__ int   g_deg[MAXN];            // per-node in-degree
__device__ int   g_off[MAXN + 1];        // CSR offsets (exclusive scan of deg)
__device__ int   g_cursor[MAXN];         // scatter cursors
__device__ int   g_csr_src[MAXE];        // src indices grouped by dst
__device__ float g_maxdiff[(size_t)MAXN * C];  // finalized x[d] - min_src (0 if no edges)

// ---------------------------------------------------------------------------
// Kernel 1: zero the degree histogram
// ---------------------------------------------------------------------------
__global__ void zero_deg_kernel(int n) {
    int i = blockIdx.x * blockDim.x + threadIdx.x;
    if (i < n) g_deg[i] = 0;
}

// ---------------------------------------------------------------------------
// Kernel 2: histogram of dst
// ---------------------------------------------------------------------------
__global__ void hist_kernel(const int* __restrict__ dst, int E) {
    int e = blockIdx.x * blockDim.x + threadIdx.x;
    if (e < E) atomicAdd(&g_deg[dst[e]], 1);
}

// ---------------------------------------------------------------------------
// Kernel 3: single-block exclusive scan of g_deg -> g_off, g_cursor
// 1024 threads, each owns a contiguous chunk; Hillis-Steele over chunk sums.
// ---------------------------------------------------------------------------
__global__ void scan_kernel(int n) {
    __shared__ int sums[1024];
    int t = threadIdx.x;
    int chunk = (n + 1023) / 1024;
    int lo = t * chunk;
    int hi = min(lo + chunk, n);

    int s = 0;
    for (int i = lo; i < hi; i++) s += g_deg[i];
    sums[t] = s;
    __syncthreads();

    for (int off = 1; off < 1024; off <<= 1) {
        int v = (t >= off) ? sums[t - off] : 0;
        __syncthreads();
        sums[t] += v;
        __syncthreads();
    }

    int excl = (t == 0) ? 0 : sums[t - 1];
    for (int i = lo; i < hi; i++) {
        int d = g_deg[i];
        g_off[i] = excl;
        g_cursor[i] = excl;
        excl += d;
    }
    if (t == 1023) g_off[n] = excl;   // total (chunk 1023 is empty or last)
}

// ---------------------------------------------------------------------------
// Kernel 4: scatter src into CSR order
// ---------------------------------------------------------------------------
__global__ void scatter_kernel(const int* __restrict__ src,
                               const int* __restrict__ dst, int E) {
    int e = blockIdx.x * blockDim.x + threadIdx.x;
    if (e < E) {
        int d = dst[e];
        int pos = atomicAdd(&g_cursor[d], 1);
        g_csr_src[pos] = src[e];
    }
}

// ---------------------------------------------------------------------------
// Kernel 5: per-node segment-min of x[src] rows, finalize maxdiff.
// One warp per node; lane owns 4 channels (float4). 4-edge unroll for MLP.
// ---------------------------------------------------------------------------
__global__ void aggregate_kernel(const float* __restrict__ x, int N) {
    int node = blockIdx.x * 8 + (threadIdx.x >> 5);
    if (node >= N) return;
    int lane = threadIdx.x & 31;

    int begin = g_off[node];
    int end   = g_off[node + 1];

    const float INF = __int_as_float(0x7F800000);
    float4 mn = make_float4(INF, INF, INF, INF);

    int j = begin;
    for (; j + 4 <= end; j += 4) {
        int s0 = __ldg(g_csr_src + j + 0);
        int s1 = __ldg(g_csr_src + j + 1);
        int s2 = __ldg(g_csr_src + j + 2);
        int s3 = __ldg(g_csr_src + j + 3);
        float4 a0 = __ldg((const float4*)(x + (size_t)s0 * C) + lane);
        float4 a1 = __ldg((const float4*)(x + (size_t)s1 * C) + lane);
        float4 a2 = __ldg((const float4*)(x + (size_t)s2 * C) + lane);
        float4 a3 = __ldg((const float4*)(x + (size_t)s3 * C) + lane);
        mn.x = fminf(mn.x, fminf(fminf(a0.x, a1.x), fminf(a2.x, a3.x)));
        mn.y = fminf(mn.y, fminf(fminf(a0.y, a1.y), fminf(a2.y, a3.y)));
        mn.z = fminf(mn.z, fminf(fminf(a0.z, a1.z), fminf(a2.z, a3.z)));
        mn.w = fminf(mn.w, fminf(fminf(a0.w, a1.w), fminf(a2.w, a3.w)));
    }
    for (; j < end; j++) {
        int s0 = __ldg(g_csr_src + j);
        float4 a0 = __ldg((const float4*)(x + (size_t)s0 * C) + lane);
        mn.x = fminf(mn.x, a0.x);
        mn.y = fminf(mn.y, a0.y);
        mn.z = fminf(mn.z, a0.z);
        mn.w = fminf(mn.w, a0.w);
    }

    float4 md;
    if (end > begin) {
        float4 xd = __ldg((const float4*)(x + (size_t)node * C) + lane);
        md = make_float4(xd.x - mn.x, xd.y - mn.y, xd.z - mn.z, xd.w - mn.w);
    } else {
        md = make_float4(0.f, 0.f, 0.f, 0.f);
    }
    *((float4*)(g_maxdiff + (size_t)node * C) + lane) = md;
}

// ---------------------------------------------------------------------------
// Kernel 6: out = relu([x | maxdiff] @ W + b)
// BM=64, BN=128 (full), BK=16. 256 threads, each computes 8 rows x 4 cols.
// ---------------------------------------------------------------------------
#define BM 64
#define BK 16
#define BN 128

__global__ void gemm_kernel(const float* __restrict__ x,
                            const float* __restrict__ W,
                            const float* __restrict__ bias,
                            float* __restrict__ out,
                            int N) {
    __shared__ float As[BM][BK + 1];
    __shared__ float Bs[BK][BN];

    int t  = threadIdx.x;
    int m0 = blockIdx.x * BM;
    int tc = t & 31;        // 32 col-groups of 4
    int tr = t >> 5;        // 8 row-groups of 8
    int c0 = tc * 4;
    int r0 = tr * 8;

    float acc[8][4];
#pragma unroll
    for (int r = 0; r < 8; r++)
#pragma unroll
        for (int j = 0; j < 4; j++) acc[r][j] = 0.0f;

    for (int k0 = 0; k0 < 2 * C; k0 += BK) {
        // A tile: 64x16, cols k<128 from x, k>=128 from g_maxdiff (finalized).
#pragma unroll
        for (int i = 0; i < 4; i++) {
            int idx = t + i * 256;
            int mm  = idx >> 4;
            int kk  = idx & 15;
            int gm  = m0 + mm;
            int gk  = k0 + kk;
            float v = 0.0f;
            if (gm < N) {
                if (gk < C)
                    v = __ldg(x + (size_t)gm * C + gk);
                else
                    v = g_maxdiff[(size_t)gm * C + (gk - C)];
            }
            As[mm][kk] = v;
        }
        // B tile: 16x128, coalesced.
#pragma unroll
        for (int i = 0; i < 8; i++) {
            int idx = t + i * 256;
            int nn  = idx & 127;
            int kk  = idx >> 7;
            Bs[kk][nn] = __ldg(W + (size_t)(k0 + kk) * BN + nn);
        }
        __syncthreads();

#pragma unroll
        for (int kk = 0; kk < BK; kk++) {
            float4 bv = *(const float4*)&Bs[kk][c0];
#pragma unroll
            for (int r = 0; r < 8; r++) {
                float a = As[r0 + r][kk];
                acc[r][0] = fmaf(a, bv.x, acc[r][0]);
                acc[r][1] = fmaf(a, bv.y, acc[r][1]);
                acc[r][2] = fmaf(a, bv.z, acc[r][2]);
                acc[r][3] = fmaf(a, bv.w, acc[r][3]);
            }
        }
        __syncthreads();
    }

    float4 bv = __ldg((const float4*)bias + tc);
#pragma unroll
    for (int r = 0; r < 8; r++) {
        int gm = m0 + r0 + r;
        if (gm < N) {
            float4 o;
            o.x = fmaxf(acc[r][0] + bv.x, 0.0f);
            o.y = fmaxf(acc[r][1] + bv.y, 0.0f);
            o.z = fmaxf(acc[r][2] + bv.z, 0.0f);
            o.w = fmaxf(acc[r][3] + bv.w, 0.0f);
            *(float4*)(out + (size_t)gm * BN + c0) = o;
        }
    }
}

// ---------------------------------------------------------------------------
// Launch
// ---------------------------------------------------------------------------
extern "C" void kernel_launch(void* const* d_in, const int* in_sizes, int n_in,
                              void* d_out, int out_size) {
    const float* x    = (const float*)d_in[0];
    const float* W    = (const float*)d_in[1];
    const float* bias = (const float*)d_in[2];
    const int*   src  = (const int*)d_in[3];
    const int*   dst  = (const int*)d_in[4];
    float*       out  = (float*)d_out;

    int N = in_sizes[0] / C;      // 100000
    int E = in_sizes[3];          // 1600000

    zero_deg_kernel<<<(N + 255) / 256, 256>>>(N);
    hist_kernel<<<(E + 255) / 256, 256>>>(dst, E);
    scan_kernel<<<1, 1024>>>(N);
    scatter_kernel<<<(E + 255) / 256, 256>>>(src, dst, E);

    int ablocks = (N + 7) / 8;    // 8 warps per block, 1 warp per node
    aggregate_kernel<<<ablocks, 256>>>(x, N);

    int gblocks = (N + BM - 1) / BM;
    gemm_kernel<<<gblocks, 256>>>(x, W, bias, out, N);
}

// round 5
// speedup vs baseline: 1.8211x; 1.6428x over previous
#include <cuda_runtime.h>
#include <cuda_bf16.h>
#include <cstdint>
#include <math.h>

#define C 128
#define MAXN 100000
#define MAXE 1600000

// ---------------------------------------------------------------------------
// Scratch
// ---------------------------------------------------------------------------
__device__ int            g_deg[MAXN];
__device__ int            g_off[MAXN + 1];
__device__ int            g_cursor[MAXN];
__device__ int            g_csr_src[MAXE];
__device__ float          g_maxdiff[(size_t)MAXN * C];
__device__ __nv_bfloat16  g_Wh[C * 2 * C];   // [n][k] transposed, hi part
__device__ __nv_bfloat16  g_Wl[C * 2 * C];   // [n][k] transposed, lo part

// ---------------------------------------------------------------------------
// Front-end kernels
// ---------------------------------------------------------------------------
__global__ void zero_deg_kernel(int n) {
    int i = blockIdx.x * blockDim.x + threadIdx.x;
    if (i < n) g_deg[i] = 0;
}
__global__ void hist_kernel(const int* __restrict__ dst, int E) {
    int e = blockIdx.x * blockDim.x + threadIdx.x;
    if (e < E) atomicAdd(&g_deg[dst[e]], 1);
}
__global__ void scan_kernel(int n) {
    __shared__ int sums[1024];
    int t = threadIdx.x;
    int chunk = (n + 1023) / 1024;
    int lo = t * chunk, hi = min(lo + chunk, n);
    int s = 0;
    for (int i = lo; i < hi; i++) s += g_deg[i];
    sums[t] = s;
    __syncthreads();
    for (int off = 1; off < 1024; off <<= 1) {
        int v = (t >= off) ? sums[t - off] : 0;
        __syncthreads();
        sums[t] += v;
        __syncthreads();
    }
    int excl = (t == 0) ? 0 : sums[t - 1];
    for (int i = lo; i < hi; i++) {
        int d = g_deg[i];
        g_off[i] = excl;
        g_cursor[i] = excl;
        excl += d;
    }
    if (t == 1023) g_off[n] = excl;
}
__global__ void scatter_kernel(const int* __restrict__ src,
                               const int* __restrict__ dst, int E) {
    int e = blockIdx.x * blockDim.x + threadIdx.x;
    if (e < E) {
        int d = dst[e];
        int pos = atomicAdd(&g_cursor[d], 1);
        g_csr_src[pos] = src[e];
    }
}
__global__ void aggregate_kernel(const float* __restrict__ x, int N) {
    int node = blockIdx.x * 8 + (threadIdx.x >> 5);
    if (node >= N) return;
    int lane = threadIdx.x & 31;
    int begin = g_off[node], end = g_off[node + 1];
    const float INF = __int_as_float(0x7F800000);
    float4 mn = make_float4(INF, INF, INF, INF);
    int j = begin;
    for (; j + 4 <= end; j += 4) {
        int s0 = __ldg(g_csr_src + j + 0);
        int s1 = __ldg(g_csr_src + j + 1);
        int s2 = __ldg(g_csr_src + j + 2);
        int s3 = __ldg(g_csr_src + j + 3);
        float4 a0 = __ldg((const float4*)(x + (size_t)s0 * C) + lane);
        float4 a1 = __ldg((const float4*)(x + (size_t)s1 * C) + lane);
        float4 a2 = __ldg((const float4*)(x + (size_t)s2 * C) + lane);
        float4 a3 = __ldg((const float4*)(x + (size_t)s3 * C) + lane);
        mn.x = fminf(mn.x, fminf(fminf(a0.x, a1.x), fminf(a2.x, a3.x)));
        mn.y = fminf(mn.y, fminf(fminf(a0.y, a1.y), fminf(a2.y, a3.y)));
        mn.z = fminf(mn.z, fminf(fminf(a0.z, a1.z), fminf(a2.z, a3.z)));
        mn.w = fminf(mn.w, fminf(fminf(a0.w, a1.w), fminf(a2.w, a3.w)));
    }
    for (; j < end; j++) {
        int s0 = __ldg(g_csr_src + j);
        float4 a0 = __ldg((const float4*)(x + (size_t)s0 * C) + lane);
        mn.x = fminf(mn.x, a0.x); mn.y = fminf(mn.y, a0.y);
        mn.z = fminf(mn.z, a0.z); mn.w = fminf(mn.w, a0.w);
    }
    float4 md;
    if (end > begin) {
        float4 xd = __ldg((const float4*)(x + (size_t)node * C) + lane);
        md = make_float4(xd.x - mn.x, xd.y - mn.y, xd.z - mn.z, xd.w - mn.w);
    } else {
        md = make_float4(0.f, 0.f, 0.f, 0.f);
    }
    *((float4*)(g_maxdiff + (size_t)node * C) + lane) = md;
}

// ---------------------------------------------------------------------------
// W split: W[256][128] fp32 -> g_Wh/g_Wl [n][k] bf16 (hi/lo decomposition)
// ---------------------------------------------------------------------------
__global__ void wsplit_kernel(const float* __restrict__ W) {
    int idx = blockIdx.x * blockDim.x + threadIdx.x;
    if (idx < 2 * C * C) {
        int k = idx >> 7, n = idx & 127;
        float v = __ldg(W + idx);
        __nv_bfloat16 hi = __float2bfloat16(v);
        __nv_bfloat16 lo = __float2bfloat16(v - __bfloat162float(hi));
        g_Wh[n * 2 * C + k] = hi;
        g_Wl[n * 2 * C + k] = lo;
    }
}

// ---------------------------------------------------------------------------
// Tensor-core GEMM via portable mma.sync (bf16 hi/lo split, fp32 accum):
//   out = relu([x | maxdiff] @ W + b)
// CTA tile 128(M) x 128(N), K=256 in 4 chunks of 64, single smem buffer.
// 8 warps = 4(M) x 2(N); warp tile 32x64 = 2x8 m16n8k16 tiles.
// ---------------------------------------------------------------------------
#define KC   64
#define AST  72                     // smem k-stride in bf16 (conflict-free)
#define TILE_BYTES (128 * AST * 2)  // 18432
#define SM_AHI 0
#define SM_ALO (1 * TILE_BYTES)
#define SM_BHI (2 * TILE_BYTES)
#define SM_BLO (3 * TILE_BYTES)
#define SMEM_TOTAL (4 * TILE_BYTES) // 73728

__device__ __forceinline__ void mma_bf16(float* d, const uint32_t* a,
                                         uint32_t b0, uint32_t b1) {
    asm volatile(
        "mma.sync.aligned.m16n8k16.row.col.f32.bf16.bf16.f32 "
        "{%0,%1,%2,%3}, {%4,%5,%6,%7}, {%8,%9}, {%0,%1,%2,%3};"
        : "+f"(d[0]), "+f"(d[1]), "+f"(d[2]), "+f"(d[3])
        : "r"(a[0]), "r"(a[1]), "r"(a[2]), "r"(a[3]), "r"(b0), "r"(b1));
}

__global__ void __launch_bounds__(256, 2)
gemm_mma_kernel(const float* __restrict__ x,
                const float* __restrict__ bias,
                float* __restrict__ out,
                int N) {
    extern __shared__ char smem[];
    int t    = threadIdx.x;
    int wid  = t >> 5;
    int lane = t & 31;
    int wm   = wid >> 1;          // 0..3 (M group)
    int wn   = wid & 1;           // 0..1 (N group)
    int m0   = blockIdx.x * 128;
    int mrow = lane >> 2;         // 0..7
    int kq   = (lane & 3) * 2;    // 0,2,4,6

    float acc[2][8][4];
#pragma unroll
    for (int mt = 0; mt < 2; mt++)
#pragma unroll
        for (int nt = 0; nt < 8; nt++)
#pragma unroll
            for (int j = 0; j < 4; j++) acc[mt][nt][j] = 0.0f;

    for (int ch = 0; ch < 4; ch++) {
        // ---- A chunk: 128 rows x 64 k floats = 2048 float4 slots (8 iters) ----
        {
            const float* Asrc = (ch < 2) ? x : g_maxdiff;
            int kbase = (ch & 1) * KC;
#pragma unroll
            for (int i = 0; i < 8; i++) {
                int f   = t + i * 256;        // 0..2047
                int row = f >> 4;             // 0..127
                int c4  = f & 15;             // 0..15
                int gm  = m0 + row;
                float4 v = make_float4(0.f, 0.f, 0.f, 0.f);
                if (gm < N)
                    v = __ldg((const float4*)(Asrc + (size_t)gm * C + kbase) + c4);
                __nv_bfloat162 h01 = __floats2bfloat162_rn(v.x, v.y);
                __nv_bfloat162 h23 = __floats2bfloat162_rn(v.z, v.w);
                __nv_bfloat162 l01 = __floats2bfloat162_rn(
                    v.x - __bfloat162float(__low2bfloat16(h01)),
                    v.y - __bfloat162float(__high2bfloat16(h01)));
                __nv_bfloat162 l23 = __floats2bfloat162_rn(
                    v.z - __bfloat162float(__low2bfloat16(h23)),
                    v.w - __bfloat162float(__high2bfloat16(h23)));
                size_t off = (size_t)(row * AST + c4 * 4) * 2;  // bytes
                *(uint2*)(smem + SM_AHI + off) =
                    make_uint2(*(uint32_t*)&h01, *(uint32_t*)&h23);
                *(uint2*)(smem + SM_ALO + off) =
                    make_uint2(*(uint32_t*)&l01, *(uint32_t*)&l23);
            }
        }
        // ---- B chunk: 128 n-rows x 64 k bf16 = 1024 uint4 slots (4 iters) ----
        {
            int kbase = ch * KC;
#pragma unroll
            for (int i = 0; i < 4; i++) {
                int f  = t + i * 256;          // 0..1023
                int n  = f >> 3;
                int c8 = f & 7;
                uint4 hb = *(const uint4*)(g_Wh + (size_t)n * 2 * C + kbase + c8 * 8);
                uint4 lb = *(const uint4*)(g_Wl + (size_t)n * 2 * C + kbase + c8 * 8);
                size_t off = (size_t)(n * AST + c8 * 8) * 2;   // 16B aligned
                *(uint4*)(smem + SM_BHI + off) = hb;
                *(uint4*)(smem + SM_BLO + off) = lb;
            }
        }
        __syncthreads();

        // ---- compute: 4 k-steps of 16 ----
#pragma unroll
        for (int ks = 0; ks < 4; ks++) {
            uint32_t ah[2][4], al[2][4];
#pragma unroll
            for (int mt = 0; mt < 2; mt++) {
                int row = wm * 32 + mt * 16 + mrow;
                size_t o  = (size_t)(row * AST + ks * 16 + kq) * 2;
                size_t o8 = o + (size_t)(8 * AST) * 2;
                ah[mt][0] = *(const uint32_t*)(smem + SM_AHI + o);
                ah[mt][1] = *(const uint32_t*)(smem + SM_AHI + o8);
                ah[mt][2] = *(const uint32_t*)(smem + SM_AHI + o + 16);
                ah[mt][3] = *(const uint32_t*)(smem + SM_AHI + o8 + 16);
                al[mt][0] = *(const uint32_t*)(smem + SM_ALO + o);
                al[mt][1] = *(const uint32_t*)(smem + SM_ALO + o8);
                al[mt][2] = *(const uint32_t*)(smem + SM_ALO + o + 16);
                al[mt][3] = *(const uint32_t*)(smem + SM_ALO + o8 + 16);
            }
#pragma unroll
            for (int nt = 0; nt < 8; nt++) {
                int n = wn * 64 + nt * 8 + mrow;
                size_t o = (size_t)(n * AST + ks * 16 + kq) * 2;
                uint32_t bh0 = *(const uint32_t*)(smem + SM_BHI + o);
                uint32_t bh1 = *(const uint32_t*)(smem + SM_BHI + o + 16);
                uint32_t bl0 = *(const uint32_t*)(smem + SM_BLO + o);
                uint32_t bl1 = *(const uint32_t*)(smem + SM_BLO + o + 16);
#pragma unroll
                for (int mt = 0; mt < 2; mt++) {
                    mma_bf16(acc[mt][nt], ah[mt], bh0, bh1);
                    mma_bf16(acc[mt][nt], ah[mt], bl0, bl1);
                    mma_bf16(acc[mt][nt], al[mt], bh0, bh1);
                }
            }
        }
        __syncthreads();
    }

    // ---- epilogue: bias + relu, float2 stores ----
#pragma unroll
    for (int mt = 0; mt < 2; mt++) {
        int m = m0 + wm * 32 + mt * 16 + mrow;
#pragma unroll
        for (int nt = 0; nt < 8; nt++) {
            int n = wn * 64 + nt * 8 + (lane & 3) * 2;
            float2 bv = __ldg((const float2*)(bias + n));
            if (m < N) {
                float2 o0;
                o0.x = fmaxf(acc[mt][nt][0] + bv.x, 0.f);
                o0.y = fmaxf(acc[mt][nt][1] + bv.y, 0.f);
                *(float2*)(out + (size_t)m * C + n) = o0;
            }
            if (m + 8 < N) {
                float2 o1;
                o1.x = fmaxf(acc[mt][nt][2] + bv.x, 0.f);
                o1.y = fmaxf(acc[mt][nt][3] + bv.y, 0.f);
                *(float2*)(out + (size_t)(m + 8) * C + n) = o1;
            }
        }
    }
}

// ---------------------------------------------------------------------------
// Launch
// ---------------------------------------------------------------------------
extern "C" void kernel_launch(void* const* d_in, const int* in_sizes, int n_in,
                              void* d_out, int out_size) {
    const float* x    = (const float*)d_in[0];
    const float* W    = (const float*)d_in[1];
    const float* bias = (const float*)d_in[2];
    const int*   src  = (const int*)d_in[3];
    const int*   dst  = (const int*)d_in[4];
    float*       out  = (float*)d_out;

    int N = in_sizes[0] / C;   // 100000
    int E = in_sizes[3];       // 1600000

    cudaFuncSetAttribute(gemm_mma_kernel,
                         cudaFuncAttributeMaxDynamicSharedMemorySize, SMEM_TOTAL);

    zero_deg_kernel<<<(N + 255) / 256, 256>>>(N);
    hist_kernel<<<(E + 255) / 256, 256>>>(dst, E);
    scan_kernel<<<1, 1024>>>(N);
    scatter_kernel<<<(E + 255) / 256, 256>>>(src, dst, E);
    wsplit_kernel<<<(2 * C * C + 255) / 256, 256>>>(W);

    int ablocks = (N + 7) / 8;
    aggregate_kernel<<<ablocks, 256>>>(x, N);

    int gblocks = (N + 127) / 128;   // 782
    gemm_mma_kernel<<<gblocks, 256, SMEM_TOTAL>>>(x, bias, out, N);
}